// round 16
// baseline (speedup 1.0000x reference)
#include <cuda_runtime.h>
#include <cuda_bf16.h>

// Causal BoW = running mean along T. Shapes: B=32, T=2048, C=512, fp32.
//
// Single-pass CHAINED scan (StreamScan-style), BARRIER-FREE, VECTORIZED:
//  tile = blockIdx.x = (tk, chain): chain = b -> 32 chains; tk = chunk of
//  R=16 rows -> 128 chunks/chain; 4096 tiles.
//  128-thread CTA: each thread owns 4 consecutive columns (float4) x 16
//  rows => full C=512 per tile row, 64 data regs/thread (same as R15),
//  but 16 LDG.128 / 16 STG.128 instead of 64 scalar each: under the
//  per-warp outstanding-LDG cap, 4x fewer ld/st instructions.
//  Protocol (per thread, no barriers, no smem): publish float4 value
//  (__stcg) -> __threadfence -> flag=1; consumer polls flag with
//  ld.acquire.gpu, reads float4 (__ldcg), resets flag (consume-and-reset).
//  EARLY PROBE: flag (and value, if already set) fetched BEFORE the load
//  batch -> zero exposed chain latency in the common case.
//  Tile i spins only on tile i-32; blocks dispatch in increasing blockIdx
//  order -> progress by induction. Last tk level never publishes; every
//  set flag is reset by its unique consumer => all state returns to zero
//  after each launch. Graph-safe, no aux kernels, no allocations.
//  1/(t+1) from compile-time __constant__ table (warp-uniform -> LDCU).

#define B_DIM 32
#define T_DIM 2048
#define C_DIM 512
#define R_ROWS 16
#define CGROUP 128
#define NCHAINS 32                       // = B_DIM
#define NTK (T_DIM / R_ROWS)             // 128
#define NTILES (NCHAINS * NTK)           // 4096

// Compile-time 1/(t+1) table, 2048 entries.
#define I1(n) 1.0f/(float)((n)+1)
#define I4(n)   I1(n),   I1((n)+1),   I1((n)+2),    I1((n)+3)
#define I16(n)  I4(n),   I4((n)+4),   I4((n)+8),    I4((n)+12)
#define I64(n)  I16(n),  I16((n)+16), I16((n)+32),  I16((n)+48)
#define I256(n) I64(n),  I64((n)+64), I64((n)+128), I64((n)+192)
#define I1024(n) I256(n),I256((n)+256),I256((n)+512),I256((n)+768)
__constant__ float c_inv[T_DIM] = { I1024(0), I1024(1024) };

__device__ float4 g_val[(size_t)NTILES * CGROUP];      // 8 MB values
__device__ unsigned g_flag[(size_t)NTILES * CGROUP];   // 2 MB flags

__device__ __forceinline__ unsigned ld_acquire(const unsigned* p) {
    unsigned v;
    asm volatile("ld.acquire.gpu.global.b32 %0, [%1];"
                 : "=r"(v) : "l"(p) : "memory");
    return v;
}

__global__ void __launch_bounds__(CGROUP, 6)
causal_bow_scan(const float* __restrict__ x, float* __restrict__ out) {
    const unsigned tid = threadIdx.x;
    const unsigned vt  = blockIdx.x;            // tile id = dispatch order

    const unsigned b  = vt & (NCHAINS - 1);     // chain = batch index
    const unsigned tk = vt >> 5;                // vt / NCHAINS
    const int t0 = (int)tk * R_ROWS;

    const size_t base = (size_t)b * (T_DIM * C_DIM)
                      + (size_t)t0 * C_DIM + tid * 4u;
    const float4* __restrict__ xp = (const float4*)(x + base);
    float4* __restrict__ op = (float4*)(out + base);
    const size_t stride4 = C_DIM / 4;           // float4 elements per row

    // EARLY PROBE: poll predecessor flag (and speculatively fetch its
    // value) before the load batch, hiding the L2 round-trip.
    unsigned* flagp = nullptr;
    const float4* valp = nullptr;
    unsigned f = 0;
    float4 pre = make_float4(0.f, 0.f, 0.f, 0.f);
    if (vt >= NCHAINS) {
        const size_t pslot = (size_t)(vt - NCHAINS) * CGROUP + tid;
        flagp = &g_flag[pslot];
        valp  = &g_val[pslot];
        f = ld_acquire(flagp);
        if (f) pre = __ldcg(valp);
    }

    // Batched vector loads: 16 independent LDG.128 per thread.
    float4 v[R_ROWS];
    #pragma unroll
    for (int u = 0; u < R_ROWS; ++u)
        v[u] = __ldg(xp + (size_t)u * stride4);

    // Local inclusive scan (4 independent column chains per thread).
    #pragma unroll
    for (int u = 1; u < R_ROWS; ++u) {
        v[u].x += v[u - 1].x;  v[u].y += v[u - 1].y;
        v[u].z += v[u - 1].z;  v[u].w += v[u - 1].w;
    }

    // Resolve prefix: common case = early probe hit; otherwise spin.
    // Then consume-and-reset the flag (values are flag-guarded; no reset).
    if (vt >= NCHAINS) {
        if (!f) {
            do { f = ld_acquire(flagp); } while (!f);
            pre = __ldcg(valp);
        }
        *(volatile unsigned*)flagp = 0u;       // consume-reset
    }

    // Publish inclusive prefix — except the last tk level (no successor).
    // Published BEFORE the output stores so successors unblock early.
    if (vt < NTILES - NCHAINS) {
        const size_t slot = (size_t)vt * CGROUP + tid;
        float4 tot;
        tot.x = pre.x + v[R_ROWS - 1].x;  tot.y = pre.y + v[R_ROWS - 1].y;
        tot.z = pre.z + v[R_ROWS - 1].z;  tot.w = pre.w + v[R_ROWS - 1].w;
        __stcg(&g_val[slot], tot);
        __threadfence();                       // values before flag
        *(volatile unsigned*)&g_flag[slot] = 1u;
    }

    // Scaled output: (pre + incl) * (1/(t+1)), vectorized streaming stores.
    #pragma unroll
    for (int u = 0; u < R_ROWS; ++u) {
        const float inv = c_inv[t0 + u];
        float4 w;
        w.x = (pre.x + v[u].x) * inv;  w.y = (pre.y + v[u].y) * inv;
        w.z = (pre.z + v[u].z) * inv;  w.w = (pre.w + v[u].w) * inv;
        __stcs(op + (size_t)u * stride4, w);
    }
}

extern "C" void kernel_launch(void* const* d_in, const int* in_sizes, int n_in,
                              void* d_out, int out_size) {
    const float* x = (const float*)d_in[0];
    float* out = (float*)d_out;
    (void)in_sizes; (void)n_in; (void)out_size;

    causal_bow_scan<<<NTILES, CGROUP>>>(x, out);
}

// round 17
// speedup vs baseline: 3.0174x; 3.0174x over previous
#include <cuda_runtime.h>
#include <cuda_bf16.h>

// Causal BoW = running mean along T. Shapes: B=32, T=2048, C=512, fp32.
//
// Single-pass CHAINED scan (StreamScan-style), BARRIER-FREE, SELF-CLEANING.
// = R15 (best: 42.6us scan; depth-32 chain law) with a leaner protocol:
//   publish  = plain volatile 64-bit store (atomic for aligned 8B; value
//              and flag share the word so no ordering needed) — replaces
//              atomicExch's pointless L2 round-trip.
//   consume  = atomicExch(pred, 0): read + consume-reset fused into ONE
//              L2 operation. The early probe (issued BEFORE the 64-row
//              load batch) uses the same exchange, so in the common case
//              the prefix arrives while the loads are still in flight.
//  tile = blockIdx.x = (tk, chain): chain = (b, c-quarter) -> 128 chains;
//  tk = chunk of R=64 rows -> 32 chunks/chain; 4096 tiles; 6 CTAs/SM.
//  128-thread CTA = one thread per column, 64 rows in registers.
//  No ticket, no barriers, no shared memory; warps flow independently.
//  Tile i waits only on tile i-128; blocks dispatch in increasing order ->
//  progress by induction. Last tk level never publishes; every published
//  word is exchanged-to-zero by its unique consumer => all device state
//  returns to zero after every launch. Graph-safe, no aux kernels.
//  1/(t+1) from compile-time __constant__ table (warp-uniform -> LDCU).

#define B_DIM 32
#define T_DIM 2048
#define C_DIM 512
#define R_ROWS 64
#define CGROUP 128
#define NCHAINS 128                      // B_DIM * (C_DIM / CGROUP)
#define NTK (T_DIM / R_ROWS)             // 32
#define NTILES (NCHAINS * NTK)           // 4096

// Compile-time 1/(t+1) table, 2048 entries.
#define I1(n) 1.0f/(float)((n)+1)
#define I4(n)   I1(n),   I1((n)+1),   I1((n)+2),    I1((n)+3)
#define I16(n)  I4(n),   I4((n)+4),   I4((n)+8),    I4((n)+12)
#define I64(n)  I16(n),  I16((n)+16), I16((n)+32),  I16((n)+48)
#define I256(n) I64(n),  I64((n)+64), I64((n)+128), I64((n)+192)
#define I1024(n) I256(n),I256((n)+256),I256((n)+512),I256((n)+768)
__constant__ float c_inv[T_DIM] = { I1024(0), I1024(1024) };

__device__ unsigned long long g_incl[(size_t)NTILES * CGROUP];  // 4 MB packed

__global__ void __launch_bounds__(CGROUP, 6)
causal_bow_scan(const float* __restrict__ x, float* __restrict__ out) {
    const unsigned tid = threadIdx.x;
    const unsigned vt  = blockIdx.x;            // tile id = dispatch order

    const unsigned chain = vt & (NCHAINS - 1);
    const unsigned tk    = vt >> 7;             // vt / NCHAINS
    const unsigned b  = chain >> 2;
    const unsigned cq = chain & 3;
    const unsigned c  = cq * CGROUP + tid;
    const int t0 = (int)tk * R_ROWS;

    const size_t base = (size_t)b * (T_DIM * C_DIM)
                      + (size_t)t0 * C_DIM + c;
    const float* __restrict__ xp = x + base;
    float* __restrict__ op = out + base;

    // EARLY PROBE: fused read+reset of the predecessor slot, issued before
    // the load batch so its L2 round-trip overlaps the load/scan phase.
    unsigned long long* predp = nullptr;
    unsigned long long pk = 0ull;
    if (vt >= NCHAINS) {
        predp = &g_incl[(size_t)(vt - NCHAINS) * CGROUP + tid];
        pk = atomicExch(predp, 0ull);           // hit => slot consumed+cleared
    }

    // Batched independent loads: 64 coalesced 128B lines in flight per warp.
    float v[R_ROWS];
    #pragma unroll
    for (int u = 0; u < R_ROWS; ++u)
        v[u] = __ldg(xp + (size_t)u * C_DIM);

    // Local inclusive scan in registers.
    #pragma unroll
    for (int u = 1; u < R_ROWS; ++u)
        v[u] += v[u - 1];

    // Resolve prefix: common case = early probe already got it; otherwise
    // keep exchanging until the predecessor's word appears (each miss
    // writes 0 over 0, harmless; the hit consumes and clears the slot).
    float prefix = 0.0f;
    if (vt >= NCHAINS) {
        while ((pk >> 32) == 0ull)
            pk = atomicExch(predp, 0ull);
        prefix = __uint_as_float((unsigned)(pk & 0xFFFFFFFFu));
    }

    // Publish inclusive prefix — except the last tk level (no successor).
    // Plain volatile 8B store: atomic, fire-and-forget, no L2 round-trip.
    // Published BEFORE the 64 output stores so successors unblock early.
    if (vt < NTILES - NCHAINS) {
        const unsigned long long opk = (1ull << 32)
            | (unsigned long long)__float_as_uint(prefix + v[R_ROWS - 1]);
        *(volatile unsigned long long*)&g_incl[(size_t)vt * CGROUP + tid] = opk;
    }

    // Scaled output: (prefix + incl) * (1/(t+1)) from constant table
    // (warp-uniform index -> uniform-port load). Streaming stores.
    #pragma unroll
    for (int u = 0; u < R_ROWS; ++u)
        __stcs(op + (size_t)u * C_DIM, (prefix + v[u]) * c_inv[t0 + u]);
}

extern "C" void kernel_launch(void* const* d_in, const int* in_sizes, int n_in,
                              void* d_out, int out_size) {
    const float* x = (const float*)d_in[0];
    float* out = (float*)d_out;
    (void)in_sizes; (void)n_in; (void)out_size;

    causal_bow_scan<<<NTILES, CGROUP>>>(x, out);
}